// round 13
// baseline (speedup 1.0000x reference)
#include <cuda_runtime.h>
#include <cuda_fp16.h>
#include <math.h>
#include <stdint.h>

#define B_  8
#define T_  2048
#define NE_ 384
#define HQ_ 8
#define HKV_ 2
#define D_  48
#define MROWS (B_*T_)
#define HALF_D 24
#define KT_ 96     // attention KV tile rows

// Scratch (device globals; no allocations allowed)
__device__ __half g_xh[(size_t)MROWS*NE_];       // x in fp16
__device__ __half g_wqkvT[(size_t)576*NE_];      // [n][k] fused wq|wk|wv, transposed
__device__ __half g_woT[(size_t)NE_*NE_];        // [n][k] wo transposed
__device__ __half g_q[(size_t)B_*HQ_*T_*D_];     // [B,HQ,T,D] rope'd, scaled by log2e/sqrt(D)
__device__ __half g_k[(size_t)B_*HKV_*T_*D_];    // [B,HKV,T,D] rope'd
__device__ __half g_vT[(size_t)B_*HKV_*D_*T_];   // [B,HKV,D,T] transposed (written directly)
__device__ __half g_oh[(size_t)B_*T_*NE_];       // [B,T,NE] attention out fp16
__device__ float  g_cos[T_*HALF_D];
__device__ float  g_sin[T_*HALF_D];

// ---------------------------------------------------------------------------
__device__ __forceinline__ void mma16h(float& d0, float& d1, float& d2, float& d3,
                                       uint32_t a0, uint32_t a1, uint32_t a2, uint32_t a3,
                                       uint32_t b0, uint32_t b1) {
    asm volatile("mma.sync.aligned.m16n8k16.row.col.f32.f16.f16.f32 "
                 "{%0,%1,%2,%3},{%4,%5,%6,%7},{%8,%9},{%0,%1,%2,%3};"
                 : "+f"(d0), "+f"(d1), "+f"(d2), "+f"(d3)
                 : "r"(a0), "r"(a1), "r"(a2), "r"(a3), "r"(b0), "r"(b1));
}
__device__ __forceinline__ void cpa16(uint32_t dst, const void* src) {
    asm volatile("cp.async.cg.shared.global [%0], [%1], 16;" :: "r"(dst), "l"(src) : "memory");
}
__device__ __forceinline__ uint32_t h2bits(__half2 h) {
    return *reinterpret_cast<uint32_t*>(&h);
}
__device__ __forceinline__ float ex2(float x) {
    float y;
    asm("ex2.approx.f32 %0, %1;" : "=f"(y) : "f"(x));
    return y;
}

// ---------------------------------------------------------------------------
__global__ void rope_table_kernel() {
    int idx = blockIdx.x * blockDim.x + threadIdx.x;
    if (idx >= T_ * HALF_D) return;
    int t = idx / HALF_D, p = idx % HALF_D;
    float inv = 1.0f / powf(10000.0f, (2.0f * (float)p) / 48.0f);
    float ang = (float)t * inv;
    g_cos[idx] = (float)cos((double)ang);
    g_sin[idx] = (float)sin((double)ang);
}

// x fp32 -> fp16 (vectorized)
__global__ void conv_x_kernel(const float* __restrict__ x) {
    int i = blockIdx.x * blockDim.x + threadIdx.x;
    if (i >= MROWS * NE_ / 4) return;
    float4 v = ((const float4*)x)[i];
    __half2* dst = (__half2*)g_xh;
    dst[2*i]     = __floats2half2_rn(v.x, v.y);
    dst[2*i + 1] = __floats2half2_rn(v.z, v.w);
}

// All 4 weight transposes in one launch.
__global__ void wtrans_all_kernel(const float* __restrict__ wq, const float* __restrict__ wk,
                                  const float* __restrict__ wv, const float* __restrict__ wo) {
    __shared__ float tile[32][33];
    int bx = blockIdx.x;
    const float* W; __half* dst; int N, n0_out, nb;
    if (bx < 12)      { W = wq; dst = g_wqkvT; N = 384; n0_out = 0;   nb = bx; }
    else if (bx < 15) { W = wk; dst = g_wqkvT; N = 96;  n0_out = 384; nb = bx - 12; }
    else if (bx < 18) { W = wv; dst = g_wqkvT; N = 96;  n0_out = 480; nb = bx - 15; }
    else              { W = wo; dst = g_woT;   N = 384; n0_out = 0;   nb = bx - 18; }
    int k0 = blockIdx.y * 32, n0 = nb * 32;
    int tx = threadIdx.x & 31, ty = threadIdx.x >> 5;
    #pragma unroll
    for (int j = 0; j < 4; j++) {
        int r = ty + j * 8;
        tile[r][tx] = W[(size_t)(k0 + r) * N + n0 + tx];
    }
    __syncthreads();
    #pragma unroll
    for (int j = 0; j < 4; j++) {
        int n = ty + j * 8;
        dst[(size_t)(n0_out + n0 + n) * 384 + k0 + tx] = __float2half(tile[tx][n]);
    }
}

// ---------------------------------------------------------------------------
// fp16 tensor-core GEMM, cp.async 3-stage, BK=32, block 128x64, 8 warps 4x2.
// MODE 0: g_xh @ g_wqkvT' (N=576) -> RoPE -> g_q/g_k; V written TRANSPOSED
//         directly to g_vT via in-smem transpose (no separate vtrans pass).
// MODE 1: g_oh @ g_woT'  (N=384) -> +bias -> fp32 Cout (float4 stores).
// ---------------------------------------------------------------------------
template<int MODE>
__global__ __launch_bounds__(256) void gemm_h(
    const float* __restrict__ bias, float* __restrict__ Cout)
{
    __shared__ __align__(16) char SMEM[46080];
    __half* Asm = (__half*)SMEM;              // 3 stages [128][40]: 10240 B each
    __half* Bsm = (__half*)(SMEM + 30720);    // 3 stages [64][40]:  5120 B each

    const __half* A  = (MODE == 0) ? g_xh    : g_oh;
    const __half* BT = (MODE == 0) ? g_wqkvT : g_woT;

    int tid  = threadIdx.x;
    int lane = tid & 31, wid = tid >> 5;
    int wm = wid & 3, wn = wid >> 2;
    int group = lane >> 2, tid4 = lane & 3;
    int bm = blockIdx.y * 128;
    int bn = blockIdx.x * 64;

    uint32_t as_base = (uint32_t)__cvta_generic_to_shared(Asm);
    uint32_t bs_base = (uint32_t)__cvta_generic_to_shared(Bsm);

    auto loadTile = [&](int s, int kt) {
        #pragma unroll
        for (int i = tid; i < 512; i += 256) {
            int r = i >> 2, seg = i & 3;
            cpa16(as_base + (uint32_t)(s*10240 + r*80 + seg*16),
                  &A[(size_t)(bm + r) * NE_ + kt*32 + seg*8]);
        }
        {
            int r = tid >> 2, seg = tid & 3;
            cpa16(bs_base + (uint32_t)(s*5120 + r*80 + seg*16),
                  &BT[(size_t)(bn + r) * NE_ + kt*32 + seg*8]);
        }
        asm volatile("cp.async.commit_group;" ::: "memory");
    };

    float acc[2][4][4];
    #pragma unroll
    for (int mt = 0; mt < 2; mt++)
        #pragma unroll
        for (int nt = 0; nt < 4; nt++)
            #pragma unroll
            for (int r = 0; r < 4; r++) acc[mt][nt][r] = 0.f;

    loadTile(0, 0);
    loadTile(1, 1);

    for (int kt = 0; kt < 12; kt++) {
        int s = kt % 3;
        if (kt < 11) asm volatile("cp.async.wait_group 1;" ::: "memory");
        else         asm volatile("cp.async.wait_group 0;" ::: "memory");
        __syncthreads();
        if (kt + 2 < 12) loadTile((kt + 2) % 3, kt + 2);

        #pragma unroll
        for (int ks = 0; ks < 2; ks++) {
            uint32_t af[2][4], bf[4][2];
            #pragma unroll
            for (int mt = 0; mt < 2; mt++) {
                int row = wm * 32 + mt * 16 + group;
                af[mt][0] = *(const uint32_t*)&Asm[s*5120 + row*40 + ks*16 + 2*tid4];
                af[mt][1] = *(const uint32_t*)&Asm[s*5120 + (row+8)*40 + ks*16 + 2*tid4];
                af[mt][2] = *(const uint32_t*)&Asm[s*5120 + row*40 + ks*16 + 8 + 2*tid4];
                af[mt][3] = *(const uint32_t*)&Asm[s*5120 + (row+8)*40 + ks*16 + 8 + 2*tid4];
            }
            #pragma unroll
            for (int nt = 0; nt < 4; nt++) {
                int nn = wn * 32 + nt * 8 + group;
                bf[nt][0] = *(const uint32_t*)&Bsm[s*2560 + nn*40 + ks*16 + 2*tid4];
                bf[nt][1] = *(const uint32_t*)&Bsm[s*2560 + nn*40 + ks*16 + 8 + 2*tid4];
            }
            #pragma unroll
            for (int mt = 0; mt < 2; mt++)
                #pragma unroll
                for (int nt = 0; nt < 4; nt++)
                    mma16h(acc[mt][nt][0], acc[mt][nt][1], acc[mt][nt][2], acc[mt][nt][3],
                           af[mt][0], af[mt][1], af[mt][2], af[mt][3],
                           bf[nt][0], bf[nt][1]);
        }
        __syncthreads();
    }

    if (MODE == 1) {
        // fp32 C tile [128][68] (272 B/row, 16B-multiple -> aligned float4)
        float* Ct = (float*)SMEM;   // 128*68*4 = 34816 B
        #pragma unroll
        for (int mt = 0; mt < 2; mt++)
            #pragma unroll
            for (int nt = 0; nt < 4; nt++) {
                int cl = wn * 32 + nt * 8 + tid4 * 2;
                float b0 = bias[bn + cl], b1 = bias[bn + cl + 1];
                #pragma unroll
                for (int half = 0; half < 2; half++) {
                    int rL = wm * 32 + mt * 16 + group + half * 8;
                    *(float2*)&Ct[rL * 68 + cl] =
                        make_float2(acc[mt][nt][half*2+0] + b0, acc[mt][nt][half*2+1] + b1);
                }
            }
        __syncthreads();
        #pragma unroll
        for (int i = tid; i < 2048; i += 256) {
            int r = i >> 4, c4 = (i & 15) * 4;
            float4 v = *(float4*)&Ct[r * 68 + c4];
            *(float4*)&Cout[(size_t)(bm + r) * 384 + bn + c4] = v;
        }
    } else {
        // Q/K: RoPE -> Ht [128][68] -> warp-per-row coalesced scatter.
        // V:   transposed into Vt_s [64 cols][132] -> coalesced [d][t] rows.
        __half* Ht = (__half*)SMEM;               // 17408 B
        __half* Vt_s = (__half*)(SMEM + 17408);   // 64*132*2 = 16896 B
        const float scale = 0.14433756729740643f * 1.4426950408889634f; // /sqrt(48)*log2e
        int vbase = (bn > 480) ? (bn - 480) : 0;  // local V col offset of this block
        #pragma unroll
        for (int mt = 0; mt < 2; mt++)
            #pragma unroll
            for (int nt = 0; nt < 4; nt++) {
                int cl = wn * 32 + nt * 8 + tid4 * 2;
                int gc = bn + cl;
                #pragma unroll
                for (int half = 0; half < 2; half++) {
                    int rL = wm * 32 + mt * 16 + group + half * 8;
                    float e = acc[mt][nt][half*2+0];
                    float o = acc[mt][nt][half*2+1];
                    if (gc < 480) {   // q or k: RoPE
                        int t = (bm + rL) & 2047;
                        int lc = (gc < 384) ? gc : gc - 384;
                        int p = (lc % 48) >> 1;
                        float cc = g_cos[t*24 + p], ss = g_sin[t*24 + p];
                        float re = e*cc - o*ss, ro = e*ss + o*cc;
                        __half2 hv = (gc < 384) ? __floats2half2_rn(re*scale, ro*scale)
                                                : __floats2half2_rn(re, ro);
                        *(__half2*)&Ht[rL * 68 + cl] = hv;
                    } else {          // v: transposed smem store
                        int cv = gc - 480 - vbase;        // 0..63
                        Vt_s[cv * 132 + rL]       = __float2half(e);
                        Vt_s[(cv + 1) * 132 + rL] = __float2half(o);
                    }
                }
            }
        __syncthreads();

        // Q/K scatter (coalesced half2 per row-segment)
        {
            int lane2 = lane * 2;
            int gc = bn + lane2;
            if (gc < 480) {
                int region = (gc < 384) ? 0 : 1;
                int lc = gc - ((region == 0) ? 0 : 384);
                int hh = lc / 48, dd = lc % 48;
                __half* dstbuf = (region == 0) ? g_q : g_k;
                int nheads = (region == 0) ? 8 : 2;
                #pragma unroll
                for (int it = 0; it < 16; it++) {
                    int rL = wid * 16 + it;
                    int row = bm + rL;
                    int b = row >> 11, t = row & 2047;
                    __half2 hv = *(__half2*)&Ht[rL * 68 + lane2];
                    size_t addr = (((size_t)b * nheads + hh) * 2048 + t) * 48 + dd;
                    *(__half2*)&dstbuf[addr] = hv;
                }
            }
        }
        // V copy-out: coalesced [d][t] rows (consecutive threads -> consecutive t)
        {
            int nv = (bn == 448) ? 32 : ((bn == 512) ? 64 : 0);
            int b = bm >> 11, tb = bm & 2047;
            for (int i = tid; i < nv * 64; i += 256) {
                int cv = i >> 6, tp = i & 63;
                int dall = vbase + cv;            // V col - 480, 0..95
                int hh = dall / 48, dd = dall % 48;
                __half2 hv = *(__half2*)&Vt_s[cv * 132 + 2 * tp];
                size_t addr = (((size_t)b * 2 + hh) * 48 + dd) * 2048 + tb + 2 * tp;
                *(__half2*)&g_vT[addr] = hv;
            }
        }
    }
}

// ---------------------------------------------------------------------------
// GQA-fused flash attention, KV tile 96. One CTA = 1 kv-head x 32 q-rows x 4 heads.
// 256 threads / 8 warps; warp w -> head (w>>1), rows (w&1)*16. exp2 softmax.
// ---------------------------------------------------------------------------
__global__ __launch_bounds__(256) void attn_tc() {
    __shared__ __align__(16) __half Ksm[2][KT_][56];    // [kvrow][d]
    __shared__ __align__(16) __half Vsm[2][48][KT_+8];  // [d][kvrow]

    int tid = threadIdx.x, lane = tid & 31, w = tid >> 5;
    int group = lane >> 2, tid4 = lane & 3;
    int bhk = blockIdx.y, b = bhk >> 1, hk = bhk & 1;
    int h  = hk * 4 + (w >> 1);
    int qt = gridDim.x - 1 - blockIdx.x;    // heavy tiles first
    int m0 = qt * 32;
    int rloc0 = (w & 1) * 16 + group;

    const __half* Qp = g_q + (((size_t)b * 8 + h) * 2048 + m0) * 48;
    const __half* Kp = g_k + ((size_t)b * 2 + hk) * 2048 * 48;
    const __half* Vp = g_vT + ((size_t)b * 2 + hk) * 48 * 2048;  // [d][t]

    uint32_t ks_base = (uint32_t)__cvta_generic_to_shared(&Ksm[0][0][0]);
    uint32_t vs_base = (uint32_t)__cvta_generic_to_shared(&Vsm[0][0][0]);

    uint32_t qf[3][4];
    #pragma unroll
    for (int ks = 0; ks < 3; ks++) {
        qf[ks][0] = *(const uint32_t*)&Qp[(size_t)rloc0 * 48 + ks*16 + 2*tid4];
        qf[ks][1] = *(const uint32_t*)&Qp[(size_t)(rloc0 + 8) * 48 + ks*16 + 2*tid4];
        qf[ks][2] = *(const uint32_t*)&Qp[(size_t)rloc0 * 48 + ks*16 + 8 + 2*tid4];
        qf[ks][3] = *(const uint32_t*)&Qp[(size_t)(rloc0 + 8) * 48 + ks*16 + 8 + 2*tid4];
    }

    auto loadKV = [&](int s, int tile) {
        const __half* Kt = Kp + (size_t)tile * KT_ * 48;
        int tbase = tile * KT_;
        #pragma unroll
        for (int i = tid; i < KT_*6; i += 256) {
            int r = i / 6, seg = i % 6;
            if (tbase + r < 2048)
                cpa16(ks_base + (uint32_t)(((s*KT_ + r)*56 + seg*8) * 2),
                      Kt + (size_t)r * 48 + seg * 8);
        }
        #pragma unroll
        for (int i = tid; i < 48*(KT_/8); i += 256) {
            int d = i / 12, seg = i % 12;
            if (tbase + seg*8 < 2048)
                cpa16(vs_base + (uint32_t)(((s*48 + d)*(KT_+8) + seg*8) * 2),
                      Vp + (size_t)d * 2048 + tbase + seg * 8);
        }
        asm volatile("cp.async.commit_group;" ::: "memory");
    };

    float oacc[6][4];
    #pragma unroll
    for (int nt = 0; nt < 6; nt++)
        #pragma unroll
        for (int r = 0; r < 4; r++) oacc[nt][r] = 0.f;
    float m0r = -1.0e30f, m1r = -1.0e30f, l0r = 0.f, l1r = 0.f;

    int kend = (m0 + 31) / KT_;
    loadKV(0, 0);

    for (int tile = 0; tile <= kend; tile++) {
        int s = tile & 1;
        asm volatile("cp.async.wait_group 0;" ::: "memory");
        __syncthreads();
        if (tile + 1 <= kend) loadKV(s ^ 1, tile + 1);

        float sacc[12][4];
        #pragma unroll
        for (int nt = 0; nt < 12; nt++)
            #pragma unroll
            for (int r = 0; r < 4; r++) sacc[nt][r] = 0.f;
        #pragma unroll
        for (int ks = 0; ks < 3; ks++) {
            #pragma unroll
            for (int nt = 0; nt < 12; nt++) {
                int nn = nt * 8 + group;
                uint32_t b0 = *(const uint32_t*)&Ksm[s][nn][ks*16 + 2*tid4];
                uint32_t b1 = *(const uint32_t*)&Ksm[s][nn][ks*16 + 8 + 2*tid4];
                mma16h(sacc[nt][0], sacc[nt][1], sacc[nt][2], sacc[nt][3],
                       qf[ks][0], qf[ks][1], qf[ks][2], qf[ks][3], b0, b1);
            }
        }

        if (tile == kend) {
            int rg0 = m0 + rloc0, rg1 = rg0 + 8;
            #pragma unroll
            for (int nt = 0; nt < 12; nt++) {
                int cg = tile * KT_ + nt * 8 + tid4 * 2;
                if (cg > rg0)     sacc[nt][0] = -1.0e30f;
                if (cg + 1 > rg0) sacc[nt][1] = -1.0e30f;
                if (cg > rg1)     sacc[nt][2] = -1.0e30f;
                if (cg + 1 > rg1) sacc[nt][3] = -1.0e30f;
            }
        }

        float mx0 = -1.0e30f, mx1 = -1.0e30f;
        #pragma unroll
        for (int nt = 0; nt < 12; nt++) {
            mx0 = fmaxf(mx0, fmaxf(sacc[nt][0], sacc[nt][1]));
            mx1 = fmaxf(mx1, fmaxf(sacc[nt][2], sacc[nt][3]));
        }
        mx0 = fmaxf(mx0, __shfl_xor_sync(0xffffffffu, mx0, 1));
        mx0 = fmaxf(mx0, __shfl_xor_sync(0xffffffffu, mx0, 2));
        mx1 = fmaxf(mx1, __shfl_xor_sync(0xffffffffu, mx1, 1));
        mx1 = fmaxf(mx1, __shfl_xor_sync(0xffffffffu, mx1, 2));

        float nm0 = fmaxf(m0r, mx0), nm1 = fmaxf(m1r, mx1);
        float sc0 = ex2(m0r - nm0), sc1 = ex2(m1r - nm1);

        uint32_t ph[12][2];
        float s0 = 0.f, s1 = 0.f;
        #pragma unroll
        for (int nt = 0; nt < 12; nt++) {
            float p0 = ex2(sacc[nt][0] - nm0);
            float p1 = ex2(sacc[nt][1] - nm0);
            float p2 = ex2(sacc[nt][2] - nm1);
            float p3 = ex2(sacc[nt][3] - nm1);
            s0 += p0 + p1; s1 += p2 + p3;
            ph[nt][0] = h2bits(__floats2half2_rn(p0, p1));
            ph[nt][1] = h2bits(__floats2half2_rn(p2, p3));
        }
        s0 += __shfl_xor_sync(0xffffffffu, s0, 1);
        s0 += __shfl_xor_sync(0xffffffffu, s0, 2);
        s1 += __shfl_xor_sync(0xffffffffu, s1, 1);
        s1 += __shfl_xor_sync(0xffffffffu, s1, 2);
        l0r = l0r * sc0 + s0;  m0r = nm0;
        l1r = l1r * sc1 + s1;  m1r = nm1;

        #pragma unroll
        for (int nt = 0; nt < 6; nt++) {
            oacc[nt][0] *= sc0; oacc[nt][1] *= sc0;
            oacc[nt][2] *= sc1; oacc[nt][3] *= sc1;
        }

        #pragma unroll
        for (int kb = 0; kb < 6; kb++) {
            uint32_t a0 = ph[2*kb][0], a1 = ph[2*kb][1];
            uint32_t a2 = ph[2*kb + 1][0], a3 = ph[2*kb + 1][1];
            #pragma unroll
            for (int nt = 0; nt < 6; nt++) {
                int d = nt * 8 + group;
                uint32_t b0 = *(const uint32_t*)&Vsm[s][d][kb * 16 + 2 * tid4];
                uint32_t b1 = *(const uint32_t*)&Vsm[s][d][kb * 16 + 8 + 2 * tid4];
                mma16h(oacc[nt][0], oacc[nt][1], oacc[nt][2], oacc[nt][3],
                       a0, a1, a2, a3, b0, b1);
            }
        }
    }

    float inv0 = 1.0f / l0r, inv1 = 1.0f / l1r;
    __half* Op = g_oh + ((size_t)b * 2048 + m0 + rloc0) * 384 + h * 48;
    #pragma unroll
    for (int nt = 0; nt < 6; nt++) {
        int d = nt * 8 + 2 * tid4;
        *(__half2*)&Op[d] =
            __floats2half2_rn(oacc[nt][0] * inv0, oacc[nt][1] * inv0);
        *(__half2*)&Op[(size_t)8 * 384 + d] =
            __floats2half2_rn(oacc[nt][2] * inv1, oacc[nt][3] * inv1);
    }
}

// ---------------------------------------------------------------------------
extern "C" void kernel_launch(void* const* d_in, const int* in_sizes, int n_in,
                              void* d_out, int out_size)
{
    const float* x  = (const float*)d_in[0];
    const float* wq = (const float*)d_in[1];
    const float* wk = (const float*)d_in[2];
    const float* wv = (const float*)d_in[3];
    const float* wo = (const float*)d_in[4];
    const float* bo = (const float*)d_in[5];
    float* out = (float*)d_out;

    rope_table_kernel<<<(T_*HALF_D + 255)/256, 256>>>();
    conv_x_kernel<<<(MROWS*NE_/4 + 255)/256, 256>>>(x);
    wtrans_all_kernel<<<dim3(30, 12), 256>>>(wq, wk, wv, wo);

    // Fused QKV projection + RoPE + direct V-transpose epilogue (N=576)
    gemm_h<0><<<dim3(9, MROWS/128), 256>>>(nullptr, nullptr);

    // GQA-fused flash attention (4 heads per CTA, KV tile 96)
    attn_tc<<<dim3(T_/32, B_*HKV_), 256>>>();

    // Output projection + bias
    gemm_h<1><<<dim3(6, MROWS/128), 256>>>(bo, out);
}

// round 14
// speedup vs baseline: 1.5107x; 1.5107x over previous
#include <cuda_runtime.h>
#include <cuda_fp16.h>
#include <math.h>
#include <stdint.h>

#define B_  8
#define T_  2048
#define NE_ 384
#define HQ_ 8
#define HKV_ 2
#define D_  48
#define MROWS (B_*T_)
#define HALF_D 24
#define KT_ 96     // attention KV tile rows

// Scratch (device globals; no allocations allowed)
__device__ __half g_xh[(size_t)MROWS*NE_];       // x in fp16
__device__ __half g_wqkvT[(size_t)576*NE_];      // [n][k] fused wq|wk|wv, transposed
__device__ __half g_woT[(size_t)NE_*NE_];        // [n][k] wo transposed
__device__ __half g_q[(size_t)B_*HQ_*T_*D_];     // [B,HQ,T,D] rope'd, scaled by log2e/sqrt(D)
__device__ __half g_k[(size_t)B_*HKV_*T_*D_];    // [B,HKV,T,D] rope'd
__device__ __half g_v[(size_t)B_*HKV_*T_*D_];    // [B,HKV,T,D]
__device__ __half g_vT[(size_t)B_*HKV_*D_*T_];   // [B,HKV,D,T] transposed
__device__ __half g_oh[(size_t)B_*T_*NE_];       // [B,T,NE] attention out fp16
__device__ float  g_cos[T_*HALF_D];
__device__ float  g_sin[T_*HALF_D];

// ---------------------------------------------------------------------------
__device__ __forceinline__ void mma16h(float& d0, float& d1, float& d2, float& d3,
                                       uint32_t a0, uint32_t a1, uint32_t a2, uint32_t a3,
                                       uint32_t b0, uint32_t b1) {
    asm volatile("mma.sync.aligned.m16n8k16.row.col.f32.f16.f16.f32 "
                 "{%0,%1,%2,%3},{%4,%5,%6,%7},{%8,%9},{%0,%1,%2,%3};"
                 : "+f"(d0), "+f"(d1), "+f"(d2), "+f"(d3)
                 : "r"(a0), "r"(a1), "r"(a2), "r"(a3), "r"(b0), "r"(b1));
}
__device__ __forceinline__ void cpa16(uint32_t dst, const void* src) {
    asm volatile("cp.async.cg.shared.global [%0], [%1], 16;" :: "r"(dst), "l"(src) : "memory");
}
__device__ __forceinline__ uint32_t h2bits(__half2 h) {
    return *reinterpret_cast<uint32_t*>(&h);
}
__device__ __forceinline__ float ex2(float x) {
    float y;
    asm("ex2.approx.f32 %0, %1;" : "=f"(y) : "f"(x));
    return y;
}

// ---------------------------------------------------------------------------
__global__ void rope_table_kernel() {
    int idx = blockIdx.x * blockDim.x + threadIdx.x;
    if (idx >= T_ * HALF_D) return;
    int t = idx / HALF_D, p = idx % HALF_D;
    float inv = 1.0f / powf(10000.0f, (2.0f * (float)p) / 48.0f);
    float ang = (float)t * inv;
    g_cos[idx] = (float)cos((double)ang);
    g_sin[idx] = (float)sin((double)ang);
}

// x fp32 -> fp16 (vectorized)
__global__ void conv_x_kernel(const float* __restrict__ x) {
    int i = blockIdx.x * blockDim.x + threadIdx.x;
    if (i >= MROWS * NE_ / 4) return;
    float4 v = ((const float4*)x)[i];
    __half2* dst = (__half2*)g_xh;
    dst[2*i]     = __floats2half2_rn(v.x, v.y);
    dst[2*i + 1] = __floats2half2_rn(v.z, v.w);
}

// All 4 weight transposes in one launch.
__global__ void wtrans_all_kernel(const float* __restrict__ wq, const float* __restrict__ wk,
                                  const float* __restrict__ wv, const float* __restrict__ wo) {
    __shared__ float tile[32][33];
    int bx = blockIdx.x;
    const float* W; __half* dst; int N, n0_out, nb;
    if (bx < 12)      { W = wq; dst = g_wqkvT; N = 384; n0_out = 0;   nb = bx; }
    else if (bx < 15) { W = wk; dst = g_wqkvT; N = 96;  n0_out = 384; nb = bx - 12; }
    else if (bx < 18) { W = wv; dst = g_wqkvT; N = 96;  n0_out = 480; nb = bx - 15; }
    else              { W = wo; dst = g_woT;   N = 384; n0_out = 0;   nb = bx - 18; }
    int k0 = blockIdx.y * 32, n0 = nb * 32;
    int tx = threadIdx.x & 31, ty = threadIdx.x >> 5;
    #pragma unroll
    for (int j = 0; j < 4; j++) {
        int r = ty + j * 8;
        tile[r][tx] = W[(size_t)(k0 + r) * N + n0 + tx];
    }
    __syncthreads();
    #pragma unroll
    for (int j = 0; j < 4; j++) {
        int n = ty + j * 8;
        dst[(size_t)(n0_out + n0 + n) * 384 + k0 + tx] = __float2half(tile[tx][n]);
    }
}

// g_v [bh][t][d] -> g_vT [bh][d][t]
__global__ void vtrans_kernel() {
    __shared__ __half tile[64][56];
    int bh = blockIdx.y;
    int t0 = blockIdx.x * 64;
    int tid = threadIdx.x;
    const __half* src = g_v + (size_t)bh * 2048 * 48 + (size_t)t0 * 48;
    #pragma unroll
    for (int i = tid; i < 1536; i += 256) {
        int r = i / 24, c2 = i % 24;
        *(uint32_t*)&tile[r][c2 * 2] = ((const uint32_t*)src)[r * 24 + c2];
    }
    __syncthreads();
    __half* dst = g_vT + (size_t)bh * 48 * 2048 + t0;
    #pragma unroll
    for (int i = tid; i < 1536; i += 256) {
        int d = i / 32, tp = i % 32;
        __half2 hv = __halves2half2(tile[2 * tp][d], tile[2 * tp + 1][d]);
        *(__half2*)&dst[(size_t)d * 2048 + 2 * tp] = hv;
    }
}

// ---------------------------------------------------------------------------
// fp16 tensor-core GEMM, cp.async 3-stage, BK=32, block 128x64, 8 warps 4x2.
// MODE 0: g_xh @ g_wqkvT' (N=576) -> RoPE -> g_q/g_k/g_v fp16 (coalesced [t][d])
// MODE 1: g_oh @ g_woT'  (N=384) -> +bias -> fp32 Cout (aligned float4 stores)
// ---------------------------------------------------------------------------
template<int MODE>
__global__ __launch_bounds__(256) void gemm_h(
    const float* __restrict__ bias, float* __restrict__ Cout)
{
    __shared__ __align__(16) char SMEM[46080];
    __half* Asm = (__half*)SMEM;              // 3 stages [128][40]: 10240 B each
    __half* Bsm = (__half*)(SMEM + 30720);    // 3 stages [64][40]:  5120 B each

    const __half* A  = (MODE == 0) ? g_xh    : g_oh;
    const __half* BT = (MODE == 0) ? g_wqkvT : g_woT;

    int tid  = threadIdx.x;
    int lane = tid & 31, wid = tid >> 5;
    int wm = wid & 3, wn = wid >> 2;
    int group = lane >> 2, tid4 = lane & 3;
    int bm = blockIdx.y * 128;
    int bn = blockIdx.x * 64;

    uint32_t as_base = (uint32_t)__cvta_generic_to_shared(Asm);
    uint32_t bs_base = (uint32_t)__cvta_generic_to_shared(Bsm);

    auto loadTile = [&](int s, int kt) {
        #pragma unroll
        for (int i = tid; i < 512; i += 256) {
            int r = i >> 2, seg = i & 3;
            cpa16(as_base + (uint32_t)(s*10240 + r*80 + seg*16),
                  &A[(size_t)(bm + r) * NE_ + kt*32 + seg*8]);
        }
        {
            int r = tid >> 2, seg = tid & 3;
            cpa16(bs_base + (uint32_t)(s*5120 + r*80 + seg*16),
                  &BT[(size_t)(bn + r) * NE_ + kt*32 + seg*8]);
        }
        asm volatile("cp.async.commit_group;" ::: "memory");
    };

    float acc[2][4][4];
    #pragma unroll
    for (int mt = 0; mt < 2; mt++)
        #pragma unroll
        for (int nt = 0; nt < 4; nt++)
            #pragma unroll
            for (int r = 0; r < 4; r++) acc[mt][nt][r] = 0.f;

    loadTile(0, 0);
    loadTile(1, 1);

    for (int kt = 0; kt < 12; kt++) {
        int s = kt % 3;
        if (kt < 11) asm volatile("cp.async.wait_group 1;" ::: "memory");
        else         asm volatile("cp.async.wait_group 0;" ::: "memory");
        __syncthreads();
        if (kt + 2 < 12) loadTile((kt + 2) % 3, kt + 2);

        #pragma unroll
        for (int ks = 0; ks < 2; ks++) {
            uint32_t af[2][4], bf[4][2];
            #pragma unroll
            for (int mt = 0; mt < 2; mt++) {
                int row = wm * 32 + mt * 16 + group;
                af[mt][0] = *(const uint32_t*)&Asm[s*5120 + row*40 + ks*16 + 2*tid4];
                af[mt][1] = *(const uint32_t*)&Asm[s*5120 + (row+8)*40 + ks*16 + 2*tid4];
                af[mt][2] = *(const uint32_t*)&Asm[s*5120 + row*40 + ks*16 + 8 + 2*tid4];
                af[mt][3] = *(const uint32_t*)&Asm[s*5120 + (row+8)*40 + ks*16 + 8 + 2*tid4];
            }
            #pragma unroll
            for (int nt = 0; nt < 4; nt++) {
                int nn = wn * 32 + nt * 8 + group;
                bf[nt][0] = *(const uint32_t*)&Bsm[s*2560 + nn*40 + ks*16 + 2*tid4];
                bf[nt][1] = *(const uint32_t*)&Bsm[s*2560 + nn*40 + ks*16 + 8 + 2*tid4];
            }
            #pragma unroll
            for (int mt = 0; mt < 2; mt++)
                #pragma unroll
                for (int nt = 0; nt < 4; nt++)
                    mma16h(acc[mt][nt][0], acc[mt][nt][1], acc[mt][nt][2], acc[mt][nt][3],
                           af[mt][0], af[mt][1], af[mt][2], af[mt][3],
                           bf[nt][0], bf[nt][1]);
        }
        __syncthreads();
    }

    if (MODE == 1) {
        // fp32 C tile [128][68] (272 B/row = 16B multiple -> aligned float4)
        float* Ct = (float*)SMEM;   // 128*68*4 = 34816 B
        #pragma unroll
        for (int mt = 0; mt < 2; mt++)
            #pragma unroll
            for (int nt = 0; nt < 4; nt++) {
                int cl = wn * 32 + nt * 8 + tid4 * 2;
                float b0 = bias[bn + cl], b1 = bias[bn + cl + 1];
                #pragma unroll
                for (int half = 0; half < 2; half++) {
                    int rL = wm * 32 + mt * 16 + group + half * 8;
                    *(float2*)&Ct[rL * 68 + cl] =
                        make_float2(acc[mt][nt][half*2+0] + b0, acc[mt][nt][half*2+1] + b1);
                }
            }
        __syncthreads();
        #pragma unroll
        for (int i = tid; i < 2048; i += 256) {
            int r = i >> 4, c4 = (i & 15) * 4;
            float4 v = *(float4*)&Ct[r * 68 + c4];
            *(float4*)&Cout[(size_t)(bm + r) * 384 + bn + c4] = v;
        }
    } else {
        // RoPE in regs -> fp16 tile [128][68] -> warp-per-row coalesced scatter.
        __half* Ht = (__half*)SMEM;  // 17408 B
        const float scale = 0.14433756729740643f * 1.4426950408889634f; // /sqrt(48)*log2e
        #pragma unroll
        for (int mt = 0; mt < 2; mt++)
            #pragma unroll
            for (int nt = 0; nt < 4; nt++) {
                int cl = wn * 32 + nt * 8 + tid4 * 2;
                int gc = bn + cl;
                #pragma unroll
                for (int half = 0; half < 2; half++) {
                    int rL = wm * 32 + mt * 16 + group + half * 8;
                    float e = acc[mt][nt][half*2+0];
                    float o = acc[mt][nt][half*2+1];
                    __half2 hv;
                    if (gc < 480) {
                        int t = (bm + rL) & 2047;
                        int lc = (gc < 384) ? gc : gc - 384;
                        int p = (lc % 48) >> 1;
                        float cc = g_cos[t*24 + p], ss = g_sin[t*24 + p];
                        float re = e*cc - o*ss, ro = e*ss + o*cc;
                        hv = (gc < 384) ? __floats2half2_rn(re*scale, ro*scale)
                                        : __floats2half2_rn(re, ro);
                    } else {
                        hv = __floats2half2_rn(e, o);
                    }
                    *(__half2*)&Ht[rL * 68 + cl] = hv;
                }
            }
        __syncthreads();
        int lane2 = lane * 2;
        int gc = bn + lane2;
        int region = (gc < 384) ? 0 : ((gc < 480) ? 1 : 2);
        int lc = gc - ((region == 0) ? 0 : ((region == 1) ? 384 : 480));
        int hh = lc / 48, dd = lc % 48;
        __half* dstbuf = (region == 0) ? g_q : ((region == 1) ? g_k : g_v);
        int nheads = (region == 0) ? 8 : 2;
        #pragma unroll
        for (int it = 0; it < 16; it++) {
            int rL = wid * 16 + it;
            int row = bm + rL;
            int b = row >> 11, t = row & 2047;
            __half2 hv = *(__half2*)&Ht[rL * 68 + lane2];
            size_t addr = (((size_t)b * nheads + hh) * 2048 + t) * 48 + dd;
            *(__half2*)&dstbuf[addr] = hv;
        }
    }
}

// ---------------------------------------------------------------------------
// GQA-fused flash attention, KV tile 96. One CTA = 1 kv-head x 32 q-rows x 4 heads.
// 256 threads / 8 warps; warp w -> head (w>>1), rows (w&1)*16. exp2 softmax.
// ---------------------------------------------------------------------------
__global__ __launch_bounds__(256) void attn_tc() {
    __shared__ __align__(16) __half Ksm[2][KT_][56];    // [kvrow][d]
    __shared__ __align__(16) __half Vsm[2][48][KT_+8];  // [d][kvrow]

    int tid = threadIdx.x, lane = tid & 31, w = tid >> 5;
    int group = lane >> 2, tid4 = lane & 3;
    int bhk = blockIdx.y, b = bhk >> 1, hk = bhk & 1;
    int h  = hk * 4 + (w >> 1);
    int qt = gridDim.x - 1 - blockIdx.x;    // heavy tiles first
    int m0 = qt * 32;
    int rloc0 = (w & 1) * 16 + group;

    const __half* Qp = g_q + (((size_t)b * 8 + h) * 2048 + m0) * 48;
    const __half* Kp = g_k + ((size_t)b * 2 + hk) * 2048 * 48;
    const __half* Vp = g_vT + ((size_t)b * 2 + hk) * 48 * 2048;  // [d][t]

    uint32_t ks_base = (uint32_t)__cvta_generic_to_shared(&Ksm[0][0][0]);
    uint32_t vs_base = (uint32_t)__cvta_generic_to_shared(&Vsm[0][0][0]);

    uint32_t qf[3][4];
    #pragma unroll
    for (int ks = 0; ks < 3; ks++) {
        qf[ks][0] = *(const uint32_t*)&Qp[(size_t)rloc0 * 48 + ks*16 + 2*tid4];
        qf[ks][1] = *(const uint32_t*)&Qp[(size_t)(rloc0 + 8) * 48 + ks*16 + 2*tid4];
        qf[ks][2] = *(const uint32_t*)&Qp[(size_t)rloc0 * 48 + ks*16 + 8 + 2*tid4];
        qf[ks][3] = *(const uint32_t*)&Qp[(size_t)(rloc0 + 8) * 48 + ks*16 + 8 + 2*tid4];
    }

    auto loadKV = [&](int s, int tile) {
        const __half* Kt = Kp + (size_t)tile * KT_ * 48;
        int tbase = tile * KT_;
        #pragma unroll
        for (int i = tid; i < KT_*6; i += 256) {
            int r = i / 6, seg = i % 6;
            if (tbase + r < 2048)
                cpa16(ks_base + (uint32_t)(((s*KT_ + r)*56 + seg*8) * 2),
                      Kt + (size_t)r * 48 + seg * 8);
        }
        #pragma unroll
        for (int i = tid; i < 48*(KT_/8); i += 256) {
            int d = i / 12, seg = i % 12;
            if (tbase + seg*8 < 2048)
                cpa16(vs_base + (uint32_t)(((s*48 + d)*(KT_+8) + seg*8) * 2),
                      Vp + (size_t)d * 2048 + tbase + seg * 8);
        }
        asm volatile("cp.async.commit_group;" ::: "memory");
    };

    float oacc[6][4];
    #pragma unroll
    for (int nt = 0; nt < 6; nt++)
        #pragma unroll
        for (int r = 0; r < 4; r++) oacc[nt][r] = 0.f;
    float m0r = -1.0e30f, m1r = -1.0e30f, l0r = 0.f, l1r = 0.f;

    int kend = (m0 + 31) / KT_;
    loadKV(0, 0);

    for (int tile = 0; tile <= kend; tile++) {
        int s = tile & 1;
        asm volatile("cp.async.wait_group 0;" ::: "memory");
        __syncthreads();
        if (tile + 1 <= kend) loadKV(s ^ 1, tile + 1);

        float sacc[12][4];
        #pragma unroll
        for (int nt = 0; nt < 12; nt++)
            #pragma unroll
            for (int r = 0; r < 4; r++) sacc[nt][r] = 0.f;
        #pragma unroll
        for (int ks = 0; ks < 3; ks++) {
            #pragma unroll
            for (int nt = 0; nt < 12; nt++) {
                int nn = nt * 8 + group;
                uint32_t b0 = *(const uint32_t*)&Ksm[s][nn][ks*16 + 2*tid4];
                uint32_t b1 = *(const uint32_t*)&Ksm[s][nn][ks*16 + 8 + 2*tid4];
                mma16h(sacc[nt][0], sacc[nt][1], sacc[nt][2], sacc[nt][3],
                       qf[ks][0], qf[ks][1], qf[ks][2], qf[ks][3], b0, b1);
            }
        }

        if (tile == kend) {
            int rg0 = m0 + rloc0, rg1 = rg0 + 8;
            #pragma unroll
            for (int nt = 0; nt < 12; nt++) {
                int cg = tile * KT_ + nt * 8 + tid4 * 2;
                if (cg > rg0)     sacc[nt][0] = -1.0e30f;
                if (cg + 1 > rg0) sacc[nt][1] = -1.0e30f;
                if (cg > rg1)     sacc[nt][2] = -1.0e30f;
                if (cg + 1 > rg1) sacc[nt][3] = -1.0e30f;
            }
        }

        float mx0 = -1.0e30f, mx1 = -1.0e30f;
        #pragma unroll
        for (int nt = 0; nt < 12; nt++) {
            mx0 = fmaxf(mx0, fmaxf(sacc[nt][0], sacc[nt][1]));
            mx1 = fmaxf(mx1, fmaxf(sacc[nt][2], sacc[nt][3]));
        }
        mx0 = fmaxf(mx0, __shfl_xor_sync(0xffffffffu, mx0, 1));
        mx0 = fmaxf(mx0, __shfl_xor_sync(0xffffffffu, mx0, 2));
        mx1 = fmaxf(mx1, __shfl_xor_sync(0xffffffffu, mx1, 1));
        mx1 = fmaxf(mx1, __shfl_xor_sync(0xffffffffu, mx1, 2));

        float nm0 = fmaxf(m0r, mx0), nm1 = fmaxf(m1r, mx1);
        float sc0 = ex2(m0r - nm0), sc1 = ex2(m1r - nm1);

        uint32_t ph[12][2];
        float s0 = 0.f, s1 = 0.f;
        #pragma unroll
        for (int nt = 0; nt < 12; nt++) {
            float p0 = ex2(sacc[nt][0] - nm0);
            float p1 = ex2(sacc[nt][1] - nm0);
            float p2 = ex2(sacc[nt][2] - nm1);
            float p3 = ex2(sacc[nt][3] - nm1);
            s0 += p0 + p1; s1 += p2 + p3;
            ph[nt][0] = h2bits(__floats2half2_rn(p0, p1));
            ph[nt][1] = h2bits(__floats2half2_rn(p2, p3));
        }
        s0 += __shfl_xor_sync(0xffffffffu, s0, 1);
        s0 += __shfl_xor_sync(0xffffffffu, s0, 2);
        s1 += __shfl_xor_sync(0xffffffffu, s1, 1);
        s1 += __shfl_xor_sync(0xffffffffu, s1, 2);
        l0r = l0r * sc0 + s0;  m0r = nm0;
        l1r = l1r * sc1 + s1;  m1r = nm1;

        #pragma unroll
        for (int nt = 0; nt < 6; nt++) {
            oacc[nt][0] *= sc0; oacc[nt][1] *= sc0;
            oacc[nt][2] *= sc1; oacc[nt][3] *= sc1;
        }

        #pragma unroll
        for (int kb = 0; kb < 6; kb++) {
            uint32_t a0 = ph[2*kb][0], a1 = ph[2*kb][1];
            uint32_t a2 = ph[2*kb + 1][0], a3 = ph[2*kb + 1][1];
            #pragma unroll
            for (int nt = 0; nt < 6; nt++) {
                int d = nt * 8 + group;
                uint32_t b0 = *(const uint32_t*)&Vsm[s][d][kb * 16 + 2 * tid4];
                uint32_t b1 = *(const uint32_t*)&Vsm[s][d][kb * 16 + 8 + 2 * tid4];
                mma16h(oacc[nt][0], oacc[nt][1], oacc[nt][2], oacc[nt][3],
                       a0, a1, a2, a3, b0, b1);
            }
        }
    }

    float inv0 = 1.0f / l0r, inv1 = 1.0f / l1r;
    __half* Op = g_oh + ((size_t)b * 2048 + m0 + rloc0) * 384 + h * 48;
    #pragma unroll
    for (int nt = 0; nt < 6; nt++) {
        int d = nt * 8 + 2 * tid4;
        *(__half2*)&Op[d] =
            __floats2half2_rn(oacc[nt][0] * inv0, oacc[nt][1] * inv0);
        *(__half2*)&Op[(size_t)8 * 384 + d] =
            __floats2half2_rn(oacc[nt][2] * inv1, oacc[nt][3] * inv1);
    }
}

// ---------------------------------------------------------------------------
extern "C" void kernel_launch(void* const* d_in, const int* in_sizes, int n_in,
                              void* d_out, int out_size)
{
    const float* x  = (const float*)d_in[0];
    const float* wq = (const float*)d_in[1];
    const float* wk = (const float*)d_in[2];
    const float* wv = (const float*)d_in[3];
    const float* wo = (const float*)d_in[4];
    const float* bo = (const float*)d_in[5];
    float* out = (float*)d_out;

    rope_table_kernel<<<(T_*HALF_D + 255)/256, 256>>>();
    conv_x_kernel<<<(MROWS*NE_/4 + 255)/256, 256>>>(x);
    wtrans_all_kernel<<<dim3(30, 12), 256>>>(wq, wk, wv, wo);

    // Fused QKV projection + RoPE epilogue (N=576)
    gemm_h<0><<<dim3(9, MROWS/128), 256>>>(nullptr, nullptr);

    // V transpose for attention's [d][t] loader
    vtrans_kernel<<<dim3(T_/64, B_*HKV_), 256>>>();

    // GQA-fused flash attention (4 heads per CTA, KV tile 96)
    attn_tc<<<dim3(T_/32, B_*HKV_), 256>>>();

    // Output projection + bias
    gemm_h<1><<<dim3(6, MROWS/128), 256>>>(bo, out);
}